// round 1
// baseline (speedup 1.0000x reference)
#include <cuda_runtime.h>

// Problem shapes (fixed)
#define BB 32
#define NN 4096
#define DD 8
#define NEE 2048
#define DEE 4

// Device scratch (static globals; no allocation)
__device__ unsigned g_mask_int[NN];
__device__ unsigned g_mask_ext[NEE];
__device__ int g_list_int[BB][4352];
__device__ int g_list_ext[BB][2304];
__device__ int g_cnt_int[BB];
__device__ int g_cnt_ext[BB];

// ---------------------------------------------------------------------------
// Kernel 1: spike generation. X = (V - (1 + 1.8 a) >= 0); a_new = 0.98 a + X.
// Writes out row 0 (X) and row 2 (a_new). No FMA contraction on the threshold
// path so the spike decision matches unfused reference arithmetic.
// ---------------------------------------------------------------------------
__global__ void k_spike(const float* __restrict__ V, const float* __restrict__ a,
                        float* __restrict__ out) {
    int idx = blockIdx.x * blockDim.x + threadIdx.x;   // 0 .. B*N-1
    float v  = V[idx];
    float aa = a[idx];
    float th = __fadd_rn(1.0f, __fmul_rn(1.8f, aa));
    float x  = (__fadd_rn(v, -th) >= 0.0f) ? 1.0f : 0.0f;
    out[idx] = x;                                       // row 0: X
    out[2 * BB * NN + idx] = 0.98f * aa + x;            // row 2: a_new
}

// ---------------------------------------------------------------------------
// Kernel 2: per-source delay decode + batch spike bitmask.
// x_int[b,i] = (delay_i==0) ? X[b,i] : Xd[delay_i-1, b, i]
// x_ext[b,j] = Xext[delay_j, b, j]
// Stored as 32-bit masks (bit b = batch b fired).
// ---------------------------------------------------------------------------
__global__ void k_mask(const float* __restrict__ Xd, const float* __restrict__ Xext,
                       const float* __restrict__ dmap_int,
                       const float* __restrict__ dmap_ext,
                       const float* __restrict__ out /* row 0 = X */) {
    int i = blockIdx.x * blockDim.x + threadIdx.x;      // 0 .. N-1
    if (i < NN) {
        int del = 0;
#pragma unroll
        for (int d = 0; d < DD; d++)
            if (dmap_int[d * NN + i] > 0.5f) del = d;
        const float* src = (del == 0) ? out : (Xd + (size_t)(del - 1) * BB * NN);
        unsigned m = 0;
#pragma unroll 8
        for (int b = 0; b < BB; b++)
            if (src[b * NN + i] > 0.5f) m |= (1u << b);
        g_mask_int[i] = m;
    }
    if (i < NEE) {
        int del = 0;
#pragma unroll
        for (int d = 0; d < DEE; d++)
            if (dmap_ext[d * NEE + i] > 0.5f) del = d;
        const float* src = Xext + (size_t)del * BB * NEE;
        unsigned m = 0;
#pragma unroll 8
        for (int b = 0; b < BB; b++)
            if (src[b * NEE + i] > 0.5f) m |= (1u << b);
        g_mask_ext[i] = m;
    }
}

// ---------------------------------------------------------------------------
// Kernel 3: one warp per batch — ballot-compact active source indices into
// per-batch lists. Padded to a multiple of 8 with -1 sentinels. Deterministic
// (sequential warp scan, no atomics).
// ---------------------------------------------------------------------------
__global__ void k_compact() {
    int b = blockIdx.x;            // 0..31
    int lane = threadIdx.x;        // 0..31
    unsigned lt = (lane == 0) ? 0u : (0xffffffffu >> (32 - lane));

    // internal
    int base = 0;
    for (int i0 = 0; i0 < NN; i0 += 32) {
        int i = i0 + lane;
        bool act = (g_mask_int[i] >> b) & 1u;
        unsigned bal = __ballot_sync(0xffffffffu, act);
        if (act) g_list_int[b][base + __popc(bal & lt)] = i;
        base += __popc(bal);
    }
    int padded = (base + 7) & ~7;
    if (base + lane < padded) g_list_int[b][base + lane] = -1;
    if (lane == 0) g_cnt_int[b] = padded;

    // external
    base = 0;
    for (int i0 = 0; i0 < NEE; i0 += 32) {
        int i = i0 + lane;
        bool act = (g_mask_ext[i] >> b) & 1u;
        unsigned bal = __ballot_sync(0xffffffffu, act);
        if (act) g_list_ext[b][base + __popc(bal & lt)] = i;
        base += __popc(bal);
    }
    padded = (base + 7) & ~7;
    if (base + lane < padded) g_list_ext[b][base + lane] = -1;
    if (lane == 0) g_cnt_ext[b] = padded;
}

// ---------------------------------------------------------------------------
// Kernel 4: sparse row-gather accumulation + membrane update.
// Thread = one output element (b, n). acc starts at the leak/reset term
// 0.95*V*(1-X) and accumulates W rows for each active source. List entries
// are warp-uniform (same b across warp) -> broadcast loads; W loads are
// coalesced 128B. Unroll-8 for memory-level parallelism.
// ---------------------------------------------------------------------------
__global__ void __launch_bounds__(128) k_gather(
        const float* __restrict__ V,
        const float* __restrict__ W_int,
        const float* __restrict__ W_ext,
        float* __restrict__ out) {
    int n = blockIdx.x * 128 + threadIdx.x;   // column
    int b = blockIdx.y;                       // batch
    int idx = b * NN + n;

    float x = out[idx];                       // X (row 0, written by k_spike)
    float acc = 0.95f * V[idx] * (1.0f - x);

    {
        const int cnt = g_cnt_int[b];
        const int* __restrict__ lst = g_list_int[b];
        for (int k = 0; k < cnt; k += 8) {
            int   e[8];
            float w[8];
#pragma unroll
            for (int u = 0; u < 8; u++) e[u] = lst[k + u];
#pragma unroll
            for (int u = 0; u < 8; u++)
                w[u] = (e[u] >= 0) ? W_int[(size_t)e[u] * NN + n] : 0.0f;
#pragma unroll
            for (int u = 0; u < 8; u++) acc += w[u];
        }
    }
    {
        const int cnt = g_cnt_ext[b];
        const int* __restrict__ lst = g_list_ext[b];
        for (int k = 0; k < cnt; k += 8) {
            int   e[8];
            float w[8];
#pragma unroll
            for (int u = 0; u < 8; u++) e[u] = lst[k + u];
#pragma unroll
            for (int u = 0; u < 8; u++)
                w[u] = (e[u] >= 0) ? W_ext[(size_t)e[u] * NN + n] : 0.0f;
#pragma unroll
            for (int u = 0; u < 8; u++) acc += w[u];
        }
    }

    out[BB * NN + idx] = acc;                 // row 1: V_new
}

// ---------------------------------------------------------------------------
extern "C" void kernel_launch(void* const* d_in, const int* in_sizes, int n_in,
                              void* d_out, int out_size) {
    const float* V        = (const float*)d_in[0];   // [B,N]
    const float* a        = (const float*)d_in[1];   // [B,N]
    const float* Xd       = (const float*)d_in[2];   // [D,B,N]
    const float* Xext     = (const float*)d_in[3];   // [DE,B,NE]
    const float* W_int    = (const float*)d_in[4];   // [N,N]
    const float* W_ext    = (const float*)d_in[5];   // [NE,N]
    const float* dmap_int = (const float*)d_in[6];   // [D,N]
    const float* dmap_ext = (const float*)d_in[7];   // [DE,NE]
    float* out = (float*)d_out;                      // [3,B,N]

    k_spike<<<(BB * NN) / 256, 256>>>(V, a, out);
    k_mask<<<NN / 256, 256>>>(Xd, Xext, dmap_int, dmap_ext, out);
    k_compact<<<BB, 32>>>();
    dim3 grid(NN / 128, BB);
    k_gather<<<grid, 128>>>(V, W_int, W_ext, out);
}

// round 2
// speedup vs baseline: 1.4560x; 1.4560x over previous
#include <cuda_runtime.h>

// Problem shapes (fixed)
#define BB 32
#define NN 4096
#define DD 8
#define NEE 2048
#define DEE 4

// Device scratch (static globals; no allocation)
__device__ unsigned g_mask_int[NN];
__device__ unsigned g_mask_ext[NEE];
__device__ int g_list_int[BB][4352];
__device__ int g_list_ext[BB][2304];
__device__ int g_cnt_int[BB];
__device__ int g_cnt_ext[BB];

// ---------------------------------------------------------------------------
// Kernel 1: spike generation. X = (V - (1 + 1.8 a) >= 0); a_new = 0.98 a + X.
// Writes out row 0 (X) and row 2 (a_new). No FMA contraction on the threshold
// path so the spike decision matches unfused reference arithmetic.
// ---------------------------------------------------------------------------
__global__ void k_spike(const float* __restrict__ V, const float* __restrict__ a,
                        float* __restrict__ out) {
    int idx = blockIdx.x * blockDim.x + threadIdx.x;   // 0 .. B*N-1
    float v  = V[idx];
    float aa = a[idx];
    float th = __fadd_rn(1.0f, __fmul_rn(1.8f, aa));
    float x  = (__fadd_rn(v, -th) >= 0.0f) ? 1.0f : 0.0f;
    out[idx] = x;                                       // row 0: X
    out[2 * BB * NN + idx] = 0.98f * aa + x;            // row 2: a_new
}

// ---------------------------------------------------------------------------
// Kernel 2: per-source delay decode + batch spike bitmask.
// ---------------------------------------------------------------------------
__global__ void k_mask(const float* __restrict__ Xd, const float* __restrict__ Xext,
                       const float* __restrict__ dmap_int,
                       const float* __restrict__ dmap_ext,
                       const float* __restrict__ out /* row 0 = X */) {
    int i = blockIdx.x * blockDim.x + threadIdx.x;      // 0 .. N-1
    if (i < NN) {
        int del = 0;
#pragma unroll
        for (int d = 0; d < DD; d++)
            if (dmap_int[d * NN + i] > 0.5f) del = d;
        const float* src = (del == 0) ? out : (Xd + (size_t)(del - 1) * BB * NN);
        unsigned m = 0;
#pragma unroll 8
        for (int b = 0; b < BB; b++)
            if (src[b * NN + i] > 0.5f) m |= (1u << b);
        g_mask_int[i] = m;
    }
    if (i < NEE) {
        int del = 0;
#pragma unroll
        for (int d = 0; d < DEE; d++)
            if (dmap_ext[d * NEE + i] > 0.5f) del = d;
        const float* src = Xext + (size_t)del * BB * NEE;
        unsigned m = 0;
#pragma unroll 8
        for (int b = 0; b < BB; b++)
            if (src[b * NEE + i] > 0.5f) m |= (1u << b);
        g_mask_ext[i] = m;
    }
}

// ---------------------------------------------------------------------------
// Kernel 3: parallel deterministic compaction. One block (8 warps) per batch.
// Pass 1: per-warp ballot counts over its contiguous chunk. Block scan.
// Pass 2: write compacted indices at warp base offsets. Pad to multiple of 8.
// ---------------------------------------------------------------------------
__global__ void __launch_bounds__(256) k_compact() {
    int b = blockIdx.x;            // 0..31
    int tid = threadIdx.x;
    int w = tid >> 5, lane = tid & 31;
    unsigned lt = (lane == 0) ? 0u : (0xffffffffu >> (32 - lane));

    __shared__ int wcnt[8], wbase[8], s_total;

    // ---- internal: each warp owns 512 sources (16 rounds) ----
    {
        int cnt = 0;
#pragma unroll
        for (int r = 0; r < 16; r++) {
            int i = (w * 16 + r) * 32 + lane;
            bool act = (g_mask_int[i] >> b) & 1u;
            cnt += __popc(__ballot_sync(0xffffffffu, act));
        }
        if (lane == 0) wcnt[w] = cnt;
        __syncthreads();
        if (tid == 0) {
            int s = 0;
#pragma unroll
            for (int j = 0; j < 8; j++) { wbase[j] = s; s += wcnt[j]; }
            s_total = s;
        }
        __syncthreads();
        int base = wbase[w];
#pragma unroll
        for (int r = 0; r < 16; r++) {
            int i = (w * 16 + r) * 32 + lane;
            bool act = (g_mask_int[i] >> b) & 1u;
            unsigned bal = __ballot_sync(0xffffffffu, act);
            if (act) g_list_int[b][base + __popc(bal & lt)] = i;
            base += __popc(bal);
        }
        int t = s_total;
        int padded = (t + 7) & ~7;
        if (t + tid < padded) g_list_int[b][t + tid] = -1;
        if (tid == 0) g_cnt_int[b] = padded;
        __syncthreads();
    }

    // ---- external: each warp owns 256 sources (8 rounds) ----
    {
        int cnt = 0;
#pragma unroll
        for (int r = 0; r < 8; r++) {
            int i = (w * 8 + r) * 32 + lane;
            bool act = (g_mask_ext[i] >> b) & 1u;
            cnt += __popc(__ballot_sync(0xffffffffu, act));
        }
        if (lane == 0) wcnt[w] = cnt;
        __syncthreads();
        if (tid == 0) {
            int s = 0;
#pragma unroll
            for (int j = 0; j < 8; j++) { wbase[j] = s; s += wcnt[j]; }
            s_total = s;
        }
        __syncthreads();
        int base = wbase[w];
#pragma unroll
        for (int r = 0; r < 8; r++) {
            int i = (w * 8 + r) * 32 + lane;
            bool act = (g_mask_ext[i] >> b) & 1u;
            unsigned bal = __ballot_sync(0xffffffffu, act);
            if (act) g_list_ext[b][base + __popc(bal & lt)] = i;
            base += __popc(bal);
        }
        int t = s_total;
        int padded = (t + 7) & ~7;
        if (t + tid < padded) g_list_ext[b][t + tid] = -1;
        if (tid == 0) g_cnt_ext[b] = padded;
    }
}

// ---------------------------------------------------------------------------
// Kernel 4: sparse row-gather + membrane update, float4-vectorized.
// Block = (batch b, 1024-column strip). 256 threads, thread owns 4 columns.
// Active-source lists staged in shared memory; W loads are LDG.128, unroll-8
// for MLP. acc initialized with the leak/reset term.
// ---------------------------------------------------------------------------
__global__ void __launch_bounds__(256) k_gather(
        const float* __restrict__ V,
        const float* __restrict__ W_int,
        const float* __restrict__ W_ext,
        float* __restrict__ out) {
    __shared__ int s_int[4352];
    __shared__ int s_ext[2304];

    int b = blockIdx.y;
    const int cnt_i = g_cnt_int[b];
    const int cnt_e = g_cnt_ext[b];
    for (int k = threadIdx.x; k < cnt_i; k += 256) s_int[k] = g_list_int[b][k];
    for (int k = threadIdx.x; k < cnt_e; k += 256) s_ext[k] = g_list_ext[b][k];
    __syncthreads();

    int n = (blockIdx.x * 256 + threadIdx.x) * 4;     // column (float4 granule)
    int idx = b * NN + n;

    float4 x = *(const float4*)(out + idx);           // X row
    float4 v = *(const float4*)(V + idx);
    float4 acc;
    acc.x = 0.95f * v.x * (1.0f - x.x);
    acc.y = 0.95f * v.y * (1.0f - x.y);
    acc.z = 0.95f * v.z * (1.0f - x.z);
    acc.w = 0.95f * v.w * (1.0f - x.w);

    for (int k = 0; k < cnt_i; k += 8) {
        int e[8];
#pragma unroll
        for (int u = 0; u < 8; u++) e[u] = s_int[k + u];
        float4 wv[8];
#pragma unroll
        for (int u = 0; u < 8; u++) {
            if (e[u] >= 0) wv[u] = *(const float4*)(W_int + (size_t)e[u] * NN + n);
            else wv[u] = make_float4(0.f, 0.f, 0.f, 0.f);
        }
#pragma unroll
        for (int u = 0; u < 8; u++) {
            acc.x += wv[u].x; acc.y += wv[u].y; acc.z += wv[u].z; acc.w += wv[u].w;
        }
    }
    for (int k = 0; k < cnt_e; k += 8) {
        int e[8];
#pragma unroll
        for (int u = 0; u < 8; u++) e[u] = s_ext[k + u];
        float4 wv[8];
#pragma unroll
        for (int u = 0; u < 8; u++) {
            if (e[u] >= 0) wv[u] = *(const float4*)(W_ext + (size_t)e[u] * NN + n);
            else wv[u] = make_float4(0.f, 0.f, 0.f, 0.f);
        }
#pragma unroll
        for (int u = 0; u < 8; u++) {
            acc.x += wv[u].x; acc.y += wv[u].y; acc.z += wv[u].z; acc.w += wv[u].w;
        }
    }

    *(float4*)(out + BB * NN + idx) = acc;            // row 1: V_new
}

// ---------------------------------------------------------------------------
extern "C" void kernel_launch(void* const* d_in, const int* in_sizes, int n_in,
                              void* d_out, int out_size) {
    const float* V        = (const float*)d_in[0];   // [B,N]
    const float* a        = (const float*)d_in[1];   // [B,N]
    const float* Xd       = (const float*)d_in[2];   // [D,B,N]
    const float* Xext     = (const float*)d_in[3];   // [DE,B,NE]
    const float* W_int    = (const float*)d_in[4];   // [N,N]
    const float* W_ext    = (const float*)d_in[5];   // [NE,N]
    const float* dmap_int = (const float*)d_in[6];   // [D,N]
    const float* dmap_ext = (const float*)d_in[7];   // [DE,NE]
    float* out = (float*)d_out;                      // [3,B,N]

    k_spike<<<(BB * NN) / 256, 256>>>(V, a, out);
    k_mask<<<NN / 256, 256>>>(Xd, Xext, dmap_int, dmap_ext, out);
    k_compact<<<BB, 256>>>();
    dim3 grid(NN / 1024, BB);
    k_gather<<<grid, 256>>>(V, W_int, W_ext, out);
}

// round 3
// speedup vs baseline: 2.3479x; 1.6126x over previous
#include <cuda_runtime.h>

// Problem shapes (fixed)
#define BB 32
#define NN 4096
#define DD 8
#define NEE 2048
#define DEE 4

// Device scratch (static globals; no allocation)
__device__ unsigned g_mask_int[NN];
__device__ unsigned g_mask_ext[NEE];
__device__ int g_list_int[BB][4352];
__device__ int g_list_ext[BB][2304];
__device__ int g_cnt_int[BB];
__device__ int g_cnt_ext[BB];

// ---------------------------------------------------------------------------
// Kernel 1: spike generation. X = (V - (1 + 1.8 a) >= 0); a_new = 0.98 a + X.
// ---------------------------------------------------------------------------
__global__ void k_spike(const float* __restrict__ V, const float* __restrict__ a,
                        float* __restrict__ out) {
    int idx = blockIdx.x * blockDim.x + threadIdx.x;   // 0 .. B*N-1
    float v  = V[idx];
    float aa = a[idx];
    float th = __fadd_rn(1.0f, __fmul_rn(1.8f, aa));
    float x  = (__fadd_rn(v, -th) >= 0.0f) ? 1.0f : 0.0f;
    out[idx] = x;                                       // row 0: X
    out[2 * BB * NN + idx] = 0.98f * aa + x;            // row 2: a_new
}

// ---------------------------------------------------------------------------
// Kernel 2: per-source delay decode + batch spike bitmask.
// ---------------------------------------------------------------------------
__global__ void k_mask(const float* __restrict__ Xd, const float* __restrict__ Xext,
                       const float* __restrict__ dmap_int,
                       const float* __restrict__ dmap_ext,
                       const float* __restrict__ out /* row 0 = X */) {
    int i = blockIdx.x * blockDim.x + threadIdx.x;      // 0 .. N-1
    if (i < NN) {
        int del = 0;
#pragma unroll
        for (int d = 0; d < DD; d++)
            if (dmap_int[d * NN + i] > 0.5f) del = d;
        const float* src = (del == 0) ? out : (Xd + (size_t)(del - 1) * BB * NN);
        unsigned m = 0;
#pragma unroll 8
        for (int b = 0; b < BB; b++)
            if (src[b * NN + i] > 0.5f) m |= (1u << b);
        g_mask_int[i] = m;
    }
    if (i < NEE) {
        int del = 0;
#pragma unroll
        for (int d = 0; d < DEE; d++)
            if (dmap_ext[d * NEE + i] > 0.5f) del = d;
        const float* src = Xext + (size_t)del * BB * NEE;
        unsigned m = 0;
#pragma unroll 8
        for (int b = 0; b < BB; b++)
            if (src[b * NEE + i] > 0.5f) m |= (1u << b);
        g_mask_ext[i] = m;
    }
}

// ---------------------------------------------------------------------------
// Kernel 3: parallel deterministic compaction. One block (8 warps) per batch.
// Lists padded to a multiple of 16 with -1 sentinels.
// ---------------------------------------------------------------------------
__global__ void __launch_bounds__(256) k_compact() {
    int b = blockIdx.x;            // 0..31
    int tid = threadIdx.x;
    int w = tid >> 5, lane = tid & 31;
    unsigned lt = (lane == 0) ? 0u : (0xffffffffu >> (32 - lane));

    __shared__ int wcnt[8], wbase[8], s_total;

    // ---- internal: each warp owns 512 sources (16 rounds) ----
    {
        int cnt = 0;
#pragma unroll
        for (int r = 0; r < 16; r++) {
            int i = (w * 16 + r) * 32 + lane;
            bool act = (g_mask_int[i] >> b) & 1u;
            cnt += __popc(__ballot_sync(0xffffffffu, act));
        }
        if (lane == 0) wcnt[w] = cnt;
        __syncthreads();
        if (tid == 0) {
            int s = 0;
#pragma unroll
            for (int j = 0; j < 8; j++) { wbase[j] = s; s += wcnt[j]; }
            s_total = s;
        }
        __syncthreads();
        int base = wbase[w];
#pragma unroll
        for (int r = 0; r < 16; r++) {
            int i = (w * 16 + r) * 32 + lane;
            bool act = (g_mask_int[i] >> b) & 1u;
            unsigned bal = __ballot_sync(0xffffffffu, act);
            if (act) g_list_int[b][base + __popc(bal & lt)] = i;
            base += __popc(bal);
        }
        int t = s_total;
        int padded = (t + 15) & ~15;
        if (t + tid < padded) g_list_int[b][t + tid] = -1;
        if (tid == 0) g_cnt_int[b] = padded;
        __syncthreads();
    }

    // ---- external: each warp owns 256 sources (8 rounds) ----
    {
        int cnt = 0;
#pragma unroll
        for (int r = 0; r < 8; r++) {
            int i = (w * 8 + r) * 32 + lane;
            bool act = (g_mask_ext[i] >> b) & 1u;
            cnt += __popc(__ballot_sync(0xffffffffu, act));
        }
        if (lane == 0) wcnt[w] = cnt;
        __syncthreads();
        if (tid == 0) {
            int s = 0;
#pragma unroll
            for (int j = 0; j < 8; j++) { wbase[j] = s; s += wcnt[j]; }
            s_total = s;
        }
        __syncthreads();
        int base = wbase[w];
#pragma unroll
        for (int r = 0; r < 8; r++) {
            int i = (w * 8 + r) * 32 + lane;
            bool act = (g_mask_ext[i] >> b) & 1u;
            unsigned bal = __ballot_sync(0xffffffffu, act);
            if (act) g_list_ext[b][base + __popc(bal & lt)] = i;
            base += __popc(bal);
        }
        int t = s_total;
        int padded = (t + 15) & ~15;
        if (t + tid < padded) g_list_ext[b][t + tid] = -1;
        if (tid == 0) g_cnt_ext[b] = padded;
    }
}

// ---------------------------------------------------------------------------
// Kernel 4: sparse row-gather + membrane update.
// Scalar: one column per thread, 128 threads/block, grid (N/128, B) = 1024
// blocks -> ~28-32 warps/SM. Unroll-16 batches (explicit arrays) so each
// thread keeps 16 independent LDG.32 in flight (warp: 16 x 128B lines).
// Lists staged to shared once per block; hot loop reads indices via LDS.
// ---------------------------------------------------------------------------
__global__ void k_gather(
        const float* __restrict__ V,
        const float* __restrict__ W_int,
        const float* __restrict__ W_ext,
        float* __restrict__ out) {
    __shared__ int s_int[4352];
    __shared__ int s_ext[2304];

    int b = blockIdx.y;
    const int cnt_i = g_cnt_int[b];
    const int cnt_e = g_cnt_ext[b];
    for (int k = threadIdx.x; k < cnt_i; k += 128) s_int[k] = g_list_int[b][k];
    for (int k = threadIdx.x; k < cnt_e; k += 128) s_ext[k] = g_list_ext[b][k];
    __syncthreads();

    int n = blockIdx.x * 128 + threadIdx.x;   // column
    int idx = b * NN + n;

    float x = out[idx];                       // X (row 0)
    float acc0 = 0.95f * V[idx] * (1.0f - x);
    float acc1 = 0.0f;

    for (int k = 0; k < cnt_i; k += 16) {
        int e[16];
#pragma unroll
        for (int u = 0; u < 16; u++) e[u] = s_int[k + u];
        float w[16];
#pragma unroll
        for (int u = 0; u < 16; u++)
            w[u] = (e[u] >= 0) ? __ldg(W_int + (size_t)e[u] * NN + n) : 0.0f;
#pragma unroll
        for (int u = 0; u < 16; u += 2) { acc0 += w[u]; acc1 += w[u + 1]; }
    }
    for (int k = 0; k < cnt_e; k += 16) {
        int e[16];
#pragma unroll
        for (int u = 0; u < 16; u++) e[u] = s_ext[k + u];
        float w[16];
#pragma unroll
        for (int u = 0; u < 16; u++)
            w[u] = (e[u] >= 0) ? __ldg(W_ext + (size_t)e[u] * NN + n) : 0.0f;
#pragma unroll
        for (int u = 0; u < 16; u += 2) { acc0 += w[u]; acc1 += w[u + 1]; }
    }

    out[BB * NN + idx] = acc0 + acc1;         // row 1: V_new
}

// ---------------------------------------------------------------------------
extern "C" void kernel_launch(void* const* d_in, const int* in_sizes, int n_in,
                              void* d_out, int out_size) {
    const float* V        = (const float*)d_in[0];   // [B,N]
    const float* a        = (const float*)d_in[1];   // [B,N]
    const float* Xd       = (const float*)d_in[2];   // [D,B,N]
    const float* Xext     = (const float*)d_in[3];   // [DE,B,NE]
    const float* W_int    = (const float*)d_in[4];   // [N,N]
    const float* W_ext    = (const float*)d_in[5];   // [NE,N]
    const float* dmap_int = (const float*)d_in[6];   // [D,N]
    const float* dmap_ext = (const float*)d_in[7];   // [DE,NE]
    float* out = (float*)d_out;                      // [3,B,N]

    k_spike<<<(BB * NN) / 256, 256>>>(V, a, out);
    k_mask<<<NN / 256, 256>>>(Xd, Xext, dmap_int, dmap_ext, out);
    k_compact<<<BB, 256>>>();
    dim3 grid(NN / 128, BB);
    k_gather<<<grid, 128>>>(V, W_int, W_ext, out);
}